// round 1
// baseline (speedup 1.0000x reference)
#include <cuda_runtime.h>
#include <math.h>

#define DIMC   2048
#define NH     16
#define NKV    4
#define SEQ    2048
#define BATCH  2
#define HD     128

// ---------------- scratch (static device memory; no allocs) ----------------
__device__ float g_qbuf[BATCH*SEQ*NH*HD];    // [B*S, H*HD]  after x@Wq
__device__ float g_kbuf[BATCH*SEQ*NKV*HD];   // [B*S, KV*HD] after x@Wk
__device__ float g_vbuf[BATCH*SEQ*NKV*HD];   // [B*S, KV*HD] after x@Wv
__device__ float g_Qt[BATCH*NH*SEQ*HD];      // [B,H,S,HD]   normed+roped
__device__ float g_Kt[BATCH*NKV*SEQ*HD];     // [B,KV,S,HD]
__device__ float g_Vt[BATCH*NKV*SEQ*HD];     // [B,KV,S,HD]
__device__ float g_attn[BATCH*SEQ*NH*HD];    // [B*S, H*HD]  attention output

// ---------------- SGEMM: C[M,N] = A[M,K] @ B[K,N], all row-major ----------
// 128x128 tile, BK=8, 256 threads, 8x8 per thread (quad-split layout)
__global__ void __launch_bounds__(256) sgemm128(const float* __restrict__ A,
                                                const float* __restrict__ B,
                                                float* __restrict__ C,
                                                int M, int N, int K) {
    __shared__ float As[8][128];   // transposed: As[k][m]
    __shared__ float Bs[8][128];   // natural:   Bs[k][n]
    const int t  = threadIdx.x;
    const int tx = t & 15, ty = t >> 4;
    const int row0 = blockIdx.y * 128, col0 = blockIdx.x * 128;
    const int ar = t >> 1, ac = (t & 1) * 4;
    const int br = t >> 5, bc = (t & 31) * 4;
    const float* Aptr = A + (size_t)(row0 + ar) * K + ac;
    const float* Bptr = B + (size_t)br * N + col0 + bc;

    float acc[8][8];
#pragma unroll
    for (int i = 0; i < 8; i++)
#pragma unroll
        for (int j = 0; j < 8; j++) acc[i][j] = 0.f;

    for (int k0 = 0; k0 < K; k0 += 8) {
        float4 av = *(const float4*)(Aptr + k0);
        float4 bv = *(const float4*)(Bptr + (size_t)k0 * N);
        __syncthreads();
        As[ac + 0][ar] = av.x;
        As[ac + 1][ar] = av.y;
        As[ac + 2][ar] = av.z;
        As[ac + 3][ar] = av.w;
        *(float4*)(&Bs[br][bc]) = bv;
        __syncthreads();
#pragma unroll
        for (int kk = 0; kk < 8; kk++) {
            float4 a0 = *(const float4*)(&As[kk][ty * 4]);
            float4 a1 = *(const float4*)(&As[kk][64 + ty * 4]);
            float4 b0 = *(const float4*)(&Bs[kk][tx * 4]);
            float4 b1 = *(const float4*)(&Bs[kk][64 + tx * 4]);
            float a[8] = {a0.x, a0.y, a0.z, a0.w, a1.x, a1.y, a1.z, a1.w};
            float bb[8] = {b0.x, b0.y, b0.z, b0.w, b1.x, b1.y, b1.z, b1.w};
#pragma unroll
            for (int i = 0; i < 8; i++)
#pragma unroll
                for (int j = 0; j < 8; j++)
                    acc[i][j] = fmaf(a[i], bb[j], acc[i][j]);
        }
    }
#pragma unroll
    for (int ih = 0; ih < 2; ih++)
#pragma unroll
        for (int i = 0; i < 4; i++) {
            int m = row0 + ih * 64 + ty * 4 + i;
#pragma unroll
            for (int jh = 0; jh < 2; jh++) {
                float4 v;
                v.x = acc[ih * 4 + i][jh * 4 + 0];
                v.y = acc[ih * 4 + i][jh * 4 + 1];
                v.z = acc[ih * 4 + i][jh * 4 + 2];
                v.w = acc[ih * 4 + i][jh * 4 + 3];
                *(float4*)(C + (size_t)m * N + col0 + jh * 64 + tx * 4) = v;
            }
        }
}

// ---------------- RMSNorm + RoPE + head transpose --------------------------
// in:  [B*S, nh, HD]   out: [B, nh, S, HD]. One warp per (b,s,h) row.
__global__ void __launch_bounds__(256) rmsnorm_rope_k(const float* __restrict__ in,
        const float* __restrict__ g, const float* __restrict__ cs,
        const float* __restrict__ sn, float* __restrict__ out,
        int nh, int nrows) {
    int w = (blockIdx.x * 256 + threadIdx.x) >> 5;
    if (w >= nrows) return;
    int lane = threadIdx.x & 31;
    int h  = w % nh;
    int bs = w / nh;
    int b = bs / SEQ, s = bs % SEQ;
    int d = lane * 4;
    const float* row = in + (size_t)w * HD;
    float4 v = *(const float4*)(row + d);
    float ssq = v.x * v.x + v.y * v.y + v.z * v.z + v.w * v.w;
#pragma unroll
    for (int o = 16; o; o >>= 1) ssq += __shfl_xor_sync(0xffffffffu, ssq, o);
    float inv = rsqrtf(ssq * (1.f / HD) + 1e-6f);
    float4 gv = *(const float4*)(g + d);
    float y[4];
    y[0] = v.x * inv * gv.x;  y[1] = v.y * inv * gv.y;
    y[2] = v.z * inv * gv.z;  y[3] = v.w * inv * gv.w;
    float p[4];
#pragma unroll
    for (int i = 0; i < 4; i++) p[i] = __shfl_xor_sync(0xffffffffu, y[i], 16);
    float sgn = (lane < 16) ? -1.f : 1.f;
    float4 cv = *(const float4*)(cs + (size_t)s * HD + d);
    float4 sv = *(const float4*)(sn + (size_t)s * HD + d);
    float4 o4;
    o4.x = y[0] * cv.x + sgn * p[0] * sv.x;
    o4.y = y[1] * cv.y + sgn * p[1] * sv.y;
    o4.z = y[2] * cv.z + sgn * p[2] * sv.z;
    o4.w = y[3] * cv.w + sgn * p[3] * sv.w;
    *(float4*)(out + ((size_t)(b * nh + h) * SEQ + s) * HD + d) = o4;
}

// ---------------- V head transpose ------------------------------------------
// in: [B*S, KV, HD] -> out: [B, KV, S, HD]
__global__ void __launch_bounds__(256) vtrans_k(const float* __restrict__ in,
                                                float* __restrict__ out) {
    int gid = blockIdx.x * 256 + threadIdx.x;      // float4 index
    int c4 = gid & 31;
    int h  = (gid >> 5) & (NKV - 1);
    int bs = gid >> 7;
    int b = bs / SEQ, s = bs % SEQ;
    float4 v = *(const float4*)(in + (size_t)gid * 4);
    *(float4*)(out + ((size_t)(b * NKV + h) * SEQ + s) * HD + c4 * 4) = v;
}

// ---------------- Flash attention (fp32, causal) ----------------------------
// Q: [B,H,S,HD]  K,V: [B,KV,S,HD]  Out: [B*S, H*HD]
// BM=BN=64, 256 threads. Qs/Ks stored d-major [HD][64+pad].
#define QP 68
#define VP 132
#define SP 68
#define FA_SMEM ((128 * QP * 2 + 64 * VP + 64 * SP) * 4)

__global__ void __launch_bounds__(256) flash_k(const float* __restrict__ Q,
        const float* __restrict__ Kall, const float* __restrict__ Vall,
        float* __restrict__ Out) {
    extern __shared__ float sm[];
    float* Qs = sm;                 // [128][QP]  Qs[d][m]
    float* Ks = Qs + 128 * QP;      // [128][QP]  Ks[d][n]
    float* Vs = Ks + 128 * QP;      // [64][VP]   Vs[n][c]
    float* Ss = Vs + 64 * VP;       // [64][SP]   Ss[m][n]

    const int t  = threadIdx.x;
    const int qi = blockIdx.x, h = blockIdx.y, b = blockIdx.z;
    const int kvh = h >> 2;  // REP = 4
    const float* Qg    = Q    + ((size_t)(b * NH  + h  ) * SEQ + qi * 64) * HD;
    const float* Kbase = Kall +  (size_t)(b * NKV + kvh) * SEQ * HD;
    const float* Vbase = Vall +  (size_t)(b * NKV + kvh) * SEQ * HD;

    // Load Q tile transposed
#pragma unroll
    for (int p = t; p < 64 * 32; p += 256) {
        int m = p >> 5, c4 = (p & 31) * 4;
        float4 v = *(const float4*)(Qg + m * HD + c4);
        Qs[(c4 + 0) * QP + m] = v.x;
        Qs[(c4 + 1) * QP + m] = v.y;
        Qs[(c4 + 2) * QP + m] = v.z;
        Qs[(c4 + 3) * QP + m] = v.w;
    }

    const int tx = t & 15, ty = t >> 4;      // QK^T thread grid
    const int r  = t >> 2, qq = t & 3;       // softmax / O ownership
    const float scale = 0.08838834764831845f;  // 1/sqrt(128)

    float mrun = -INFINITY, lrun = 0.f;
    float4 o[8];
#pragma unroll
    for (int j = 0; j < 8; j++) o[j] = make_float4(0.f, 0.f, 0.f, 0.f);

    for (int jt = 0; jt <= qi; jt++) {
        __syncthreads();   // previous PV done reading Vs/Ss
        const float* Kt = Kbase + (size_t)jt * 64 * HD;
        const float* Vt = Vbase + (size_t)jt * 64 * HD;
#pragma unroll
        for (int p = t; p < 64 * 32; p += 256) {
            int n = p >> 5, c4 = (p & 31) * 4;
            float4 kv = *(const float4*)(Kt + n * HD + c4);
            Ks[(c4 + 0) * QP + n] = kv.x;
            Ks[(c4 + 1) * QP + n] = kv.y;
            Ks[(c4 + 2) * QP + n] = kv.z;
            Ks[(c4 + 3) * QP + n] = kv.w;
            float4 vv = *(const float4*)(Vt + n * HD + c4);
            *(float4*)(Vs + n * VP + c4) = vv;
        }
        __syncthreads();

        // S = Q K^T (64x64)
        float acc[4][4];
#pragma unroll
        for (int i = 0; i < 4; i++)
#pragma unroll
            for (int j = 0; j < 4; j++) acc[i][j] = 0.f;
        for (int d = 0; d < HD; d++) {
            float4 qa = *(const float4*)(Qs + d * QP + ty * 4);
            float4 kb = *(const float4*)(Ks + d * QP + tx * 4);
            float av[4] = {qa.x, qa.y, qa.z, qa.w};
            float bv[4] = {kb.x, kb.y, kb.z, kb.w};
#pragma unroll
            for (int i = 0; i < 4; i++)
#pragma unroll
                for (int j = 0; j < 4; j++)
                    acc[i][j] = fmaf(av[i], bv[j], acc[i][j]);
        }
        const int kbase = jt * 64;
#pragma unroll
        for (int i = 0; i < 4; i++) {
            int qrow = qi * 64 + ty * 4 + i;
            float4 sv;
            sv.x = acc[i][0] * scale + ((kbase + tx * 4 + 0) > qrow ? -1e9f : 0.f);
            sv.y = acc[i][1] * scale + ((kbase + tx * 4 + 1) > qrow ? -1e9f : 0.f);
            sv.z = acc[i][2] * scale + ((kbase + tx * 4 + 2) > qrow ? -1e9f : 0.f);
            sv.w = acc[i][3] * scale + ((kbase + tx * 4 + 3) > qrow ? -1e9f : 0.f);
            *(float4*)(Ss + (ty * 4 + i) * SP + tx * 4) = sv;
        }
        __syncthreads();

        // Online softmax: 4 threads per row
        float* srow = Ss + r * SP + qq * 16;
        float mloc = -INFINITY;
#pragma unroll
        for (int n = 0; n < 16; n++) mloc = fmaxf(mloc, srow[n]);
        mloc = fmaxf(mloc, __shfl_xor_sync(0xffffffffu, mloc, 1));
        mloc = fmaxf(mloc, __shfl_xor_sync(0xffffffffu, mloc, 2));
        float mnew = fmaxf(mrun, mloc);
        float corr = __expf(mrun - mnew);
        float lsum = 0.f;
#pragma unroll
        for (int n = 0; n < 16; n++) {
            float pe = __expf(srow[n] - mnew);
            srow[n] = pe;
            lsum += pe;
        }
        lsum += __shfl_xor_sync(0xffffffffu, lsum, 1);
        lsum += __shfl_xor_sync(0xffffffffu, lsum, 2);
        lrun = lrun * corr + lsum;
        mrun = mnew;
        __syncwarp();

        // O = O*corr + P @ V
#pragma unroll
        for (int j = 0; j < 8; j++) {
            o[j].x *= corr; o[j].y *= corr; o[j].z *= corr; o[j].w *= corr;
        }
        const float* prow = Ss + r * SP;
        for (int n = 0; n < 64; n++) {
            float pp = prow[n];
            const float4* vr = (const float4*)(Vs + n * VP) + qq;
#pragma unroll
            for (int j = 0; j < 8; j++) {
                float4 vv = vr[4 * j];
                o[j].x = fmaf(pp, vv.x, o[j].x);
                o[j].y = fmaf(pp, vv.y, o[j].y);
                o[j].z = fmaf(pp, vv.z, o[j].z);
                o[j].w = fmaf(pp, vv.w, o[j].w);
            }
        }
    }

    float invl = 1.f / lrun;
    int qrow = qi * 64 + r;
    float* op = Out + ((size_t)(b * SEQ + qrow)) * (NH * HD) + h * HD;
#pragma unroll
    for (int j = 0; j < 8; j++) {
        float4 v = o[j];
        v.x *= invl; v.y *= invl; v.z *= invl; v.w *= invl;
        *(float4*)(op + (qq + 4 * j) * 4) = v;
    }
}

// ---------------- launch -----------------------------------------------------
extern "C" void kernel_launch(void* const* d_in, const int* in_sizes, int n_in,
                              void* d_out, int out_size) {
    (void)in_sizes; (void)n_in; (void)out_size;
    const float* x  = (const float*)d_in[0];
    const float* Wq = (const float*)d_in[1];
    const float* Wk = (const float*)d_in[2];
    const float* Wv = (const float*)d_in[3];
    const float* Wo = (const float*)d_in[4];
    const float* qg = (const float*)d_in[5];
    const float* kg = (const float*)d_in[6];
    const float* cs = (const float*)d_in[7];
    const float* sn = (const float*)d_in[8];
    float* out = (float*)d_out;

    float *qb, *kb, *vb, *Qt, *Kt, *Vt, *attnb;
    cudaGetSymbolAddress((void**)&qb,    g_qbuf);
    cudaGetSymbolAddress((void**)&kb,    g_kbuf);
    cudaGetSymbolAddress((void**)&vb,    g_vbuf);
    cudaGetSymbolAddress((void**)&Qt,    g_Qt);
    cudaGetSymbolAddress((void**)&Kt,    g_Kt);
    cudaGetSymbolAddress((void**)&Vt,    g_Vt);
    cudaGetSymbolAddress((void**)&attnb, g_attn);

    const int M = BATCH * SEQ;  // 4096

    sgemm128<<<dim3((NH * HD) / 128, M / 128), 256>>>(x, Wq, qb, M, NH * HD, DIMC);
    sgemm128<<<dim3((NKV * HD) / 128, M / 128), 256>>>(x, Wk, kb, M, NKV * HD, DIMC);
    sgemm128<<<dim3((NKV * HD) / 128, M / 128), 256>>>(x, Wv, vb, M, NKV * HD, DIMC);

    rmsnorm_rope_k<<<(M * NH)  / 8, 256>>>(qb, qg, cs, sn, Qt, NH,  M * NH);
    rmsnorm_rope_k<<<(M * NKV) / 8, 256>>>(kb, kg, cs, sn, Kt, NKV, M * NKV);
    vtrans_k<<<(M * NKV * HD / 4) / 256, 256>>>(vb, Vt);

    cudaFuncSetAttribute(flash_k, cudaFuncAttributeMaxDynamicSharedMemorySize, FA_SMEM);
    flash_k<<<dim3(SEQ / 64, NH, BATCH), 256, FA_SMEM>>>(Qt, Kt, Vt, attnb);

    sgemm128<<<dim3(DIMC / 128, M / 128), 256>>>(attnb, Wo, out, M, DIMC, DIMC);
}

// round 3
// speedup vs baseline: 1.2092x; 1.2092x over previous
#include <cuda_runtime.h>
#include <math.h>
#include <stdint.h>

#define DIMC   2048
#define NH     16
#define NKV    4
#define SEQ    2048
#define BATCH  2
#define HD     128

// ---------------- scratch (static device memory; no allocs) ----------------
__device__ float g_qbuf[BATCH*SEQ*NH*HD];
__device__ float g_kbuf[BATCH*SEQ*NKV*HD];
__device__ float g_vbuf[BATCH*SEQ*NKV*HD];
__device__ float g_Qt[BATCH*NH*SEQ*HD];
__device__ float g_Kt[BATCH*NKV*SEQ*HD];
__device__ float g_Vt[BATCH*NKV*SEQ*HD];
__device__ float g_attn[BATCH*SEQ*NH*HD];
__device__ float g_WqT[DIMC*DIMC];
__device__ float g_WkT[NKV*HD*DIMC];
__device__ float g_WvT[NKV*HD*DIMC];
__device__ float g_WoT[DIMC*DIMC];

// ================= mma.sync tf32 helpers =================
__device__ __forceinline__ uint32_t f2tf(float x) {
    uint32_t r;
    asm("cvt.rna.tf32.f32 %0, %1;" : "=r"(r) : "f"(x));
    return r;
}
__device__ __forceinline__ void split_tf32(float x, uint32_t& h, uint32_t& l) {
    h = f2tf(x);
    l = f2tf(x - __uint_as_float(h));
}
__device__ __forceinline__ void mma8(float* c, const uint32_t* a, const uint32_t* b) {
    asm volatile(
        "mma.sync.aligned.m16n8k8.row.col.f32.tf32.tf32.f32 "
        "{%0,%1,%2,%3}, {%4,%5,%6,%7}, {%8,%9}, {%0,%1,%2,%3};"
        : "+f"(c[0]), "+f"(c[1]), "+f"(c[2]), "+f"(c[3])
        : "r"(a[0]), "r"(a[1]), "r"(a[2]), "r"(a[3]), "r"(b[0]), "r"(b[1]));
}

// ================= tf32 GEMM via mma.sync (3xTF32 split) =================
// C[M,N] = A[M,K] @ Bt[N,K]^T. 128x128 tile, BK=32, 256 thr, warp tile 32x64.
#define ASTR 36

__global__ void __launch_bounds__(256) tf32gemm(const float* __restrict__ A,
                                                const float* __restrict__ Bt,
                                                float* __restrict__ C,
                                                int N, int K) {
    __shared__ float As[128 * ASTR];
    __shared__ float Bs[128 * ASTR];
    const int t = threadIdx.x;
    const int wid = t >> 5, lane = t & 31;
    const int g = lane >> 2, tig = lane & 3;
    const int wm = wid & 3, wn = wid >> 2;
    const int m0w = wm * 32, n0w = wn * 64;
    const int row0 = blockIdx.y * 128, col0 = blockIdx.x * 128;
    const int tk = t & 7, tm = t >> 3;
    const float* Ag = A  + (size_t)(row0 + tm) * K + tk * 4;
    const float* Bg = Bt + (size_t)(col0 + tm) * K + tk * 4;

    float acc[2][8][4];
#pragma unroll
    for (int mf = 0; mf < 2; mf++)
#pragma unroll
        for (int nf = 0; nf < 8; nf++)
#pragma unroll
            for (int e = 0; e < 4; e++) acc[mf][nf][e] = 0.f;

    float4 pa[4], pb[4];
#pragma unroll
    for (int i = 0; i < 4; i++) {
        pa[i] = *(const float4*)(Ag + (size_t)(32 * i) * K);
        pb[i] = *(const float4*)(Bg + (size_t)(32 * i) * K);
    }

    const int CH = K / 32;
    for (int c = 0; c < CH; c++) {
        __syncthreads();
#pragma unroll
        for (int i = 0; i < 4; i++) {
            *(float4*)(&As[(tm + 32 * i) * ASTR + tk * 4]) = pa[i];
            *(float4*)(&Bs[(tm + 32 * i) * ASTR + tk * 4]) = pb[i];
        }
        __syncthreads();
        if (c + 1 < CH) {
            const int k0 = (c + 1) * 32;
#pragma unroll
            for (int i = 0; i < 4; i++) {
                pa[i] = *(const float4*)(Ag + k0 + (size_t)(32 * i) * K);
                pb[i] = *(const float4*)(Bg + k0 + (size_t)(32 * i) * K);
            }
        }
#pragma unroll
        for (int ks = 0; ks < 4; ks++) {
            const int kk = ks * 8;
            uint32_t AH[2][4], AL[2][4];
#pragma unroll
            for (int mf = 0; mf < 2; mf++)
#pragma unroll
                for (int e = 0; e < 4; e++) {
                    int m = m0w + mf * 16 + g + 8 * (e & 1);
                    int k = kk + tig + 4 * (e >> 1);
                    split_tf32(As[m * ASTR + k], AH[mf][e], AL[mf][e]);
                }
            uint32_t BH[8][2], BL[8][2];
#pragma unroll
            for (int nf = 0; nf < 8; nf++)
#pragma unroll
                for (int e = 0; e < 2; e++) {
                    int n = n0w + nf * 8 + g;
                    int k = kk + tig + 4 * e;
                    split_tf32(Bs[n * ASTR + k], BH[nf][e], BL[nf][e]);
                }
#pragma unroll
            for (int nf = 0; nf < 8; nf++)
#pragma unroll
                for (int mf = 0; mf < 2; mf++) {
                    mma8(acc[mf][nf], AH[mf], BH[nf]);
                    mma8(acc[mf][nf], AL[mf], BH[nf]);
                    mma8(acc[mf][nf], AH[mf], BL[nf]);
                }
        }
    }

    // epilogue
#pragma unroll
    for (int mf = 0; mf < 2; mf++)
#pragma unroll
        for (int nf = 0; nf < 8; nf++) {
            int r0 = row0 + m0w + mf * 16 + g;
            int cc = col0 + n0w + nf * 8 + 2 * tig;
            float2 v0 = make_float2(acc[mf][nf][0], acc[mf][nf][1]);
            float2 v1 = make_float2(acc[mf][nf][2], acc[mf][nf][3]);
            *(float2*)(C + (size_t)r0 * N + cc) = v0;
            *(float2*)(C + (size_t)(r0 + 8) * N + cc) = v1;
        }
}

// ---------------- W transpose: Wt[n][k] = W[k][n] ---------------------------
__global__ void __launch_bounds__(256) transpose_k(const float* __restrict__ W,
                                                   float* __restrict__ Wt,
                                                   int K, int N) {
    __shared__ float tile[32][33];
    int n0 = blockIdx.x * 32, k0 = blockIdx.y * 32;
    int tx = threadIdx.x & 31, ty = threadIdx.x >> 5;
#pragma unroll
    for (int i = ty; i < 32; i += 8)
        tile[i][tx] = W[(size_t)(k0 + i) * N + n0 + tx];
    __syncthreads();
#pragma unroll
    for (int i = ty; i < 32; i += 8)
        Wt[(size_t)(n0 + i) * K + k0 + tx] = tile[tx][i];
}

// ---------------- RMSNorm + RoPE + head transpose --------------------------
__global__ void __launch_bounds__(256) rmsnorm_rope_k(const float* __restrict__ in,
        const float* __restrict__ g, const float* __restrict__ cs,
        const float* __restrict__ sn, float* __restrict__ out,
        int nh, int nrows) {
    int w = (blockIdx.x * 256 + threadIdx.x) >> 5;
    if (w >= nrows) return;
    int lane = threadIdx.x & 31;
    int h  = w % nh;
    int bs = w / nh;
    int b = bs / SEQ, s = bs % SEQ;
    int d = lane * 4;
    const float* row = in + (size_t)w * HD;
    float4 v = *(const float4*)(row + d);
    float ssq = v.x * v.x + v.y * v.y + v.z * v.z + v.w * v.w;
#pragma unroll
    for (int o = 16; o; o >>= 1) ssq += __shfl_xor_sync(0xffffffffu, ssq, o);
    float inv = rsqrtf(ssq * (1.f / HD) + 1e-6f);
    float4 gv = *(const float4*)(g + d);
    float y[4];
    y[0] = v.x * inv * gv.x;  y[1] = v.y * inv * gv.y;
    y[2] = v.z * inv * gv.z;  y[3] = v.w * inv * gv.w;
    float p[4];
#pragma unroll
    for (int i = 0; i < 4; i++) p[i] = __shfl_xor_sync(0xffffffffu, y[i], 16);
    float sgn = (lane < 16) ? -1.f : 1.f;
    float4 cv = *(const float4*)(cs + (size_t)s * HD + d);
    float4 sv = *(const float4*)(sn + (size_t)s * HD + d);
    float4 o4;
    o4.x = y[0] * cv.x + sgn * p[0] * sv.x;
    o4.y = y[1] * cv.y + sgn * p[1] * sv.y;
    o4.z = y[2] * cv.z + sgn * p[2] * sv.z;
    o4.w = y[3] * cv.w + sgn * p[3] * sv.w;
    *(float4*)(out + ((size_t)(b * nh + h) * SEQ + s) * HD + d) = o4;
}

// ---------------- V head transpose ------------------------------------------
__global__ void __launch_bounds__(256) vtrans_k(const float* __restrict__ in,
                                                float* __restrict__ out) {
    int gid = blockIdx.x * 256 + threadIdx.x;
    int c4 = gid & 31;
    int h  = (gid >> 5) & (NKV - 1);
    int bs = gid >> 7;
    int b = bs / SEQ, s = bs % SEQ;
    float4 v = *(const float4*)(in + (size_t)gid * 4);
    *(float4*)(out + ((size_t)(b * NKV + h) * SEQ + s) * HD + c4 * 4) = v;
}

// ---------------- Flash attention (fp32, causal) ----------------------------
#define QP 68
#define VP 132
#define SP 68
#define FA_SMEM ((128 * QP * 2 + 64 * VP + 64 * SP) * 4)

__global__ void __launch_bounds__(256) flash_k(const float* __restrict__ Q,
        const float* __restrict__ Kall, const float* __restrict__ Vall,
        float* __restrict__ Out) {
    extern __shared__ float sm[];
    float* Qs = sm;
    float* Ks = Qs + 128 * QP;
    float* Vs = Ks + 128 * QP;
    float* Ss = Vs + 64 * VP;

    const int t  = threadIdx.x;
    const int qi = blockIdx.x, h = blockIdx.y, b = blockIdx.z;
    const int kvh = h >> 2;
    const float* Qg    = Q    + ((size_t)(b * NH  + h  ) * SEQ + qi * 64) * HD;
    const float* Kbase = Kall +  (size_t)(b * NKV + kvh) * SEQ * HD;
    const float* Vbase = Vall +  (size_t)(b * NKV + kvh) * SEQ * HD;

#pragma unroll
    for (int p = t; p < 64 * 32; p += 256) {
        int m = p >> 5, c4 = (p & 31) * 4;
        float4 v = *(const float4*)(Qg + m * HD + c4);
        Qs[(c4 + 0) * QP + m] = v.x;
        Qs[(c4 + 1) * QP + m] = v.y;
        Qs[(c4 + 2) * QP + m] = v.z;
        Qs[(c4 + 3) * QP + m] = v.w;
    }

    const int tx = t & 15, ty = t >> 4;
    const int r  = t >> 2, qq = t & 3;
    const float scale = 0.08838834764831845f;

    float mrun = -INFINITY, lrun = 0.f;
    float4 o[8];
#pragma unroll
    for (int j = 0; j < 8; j++) o[j] = make_float4(0.f, 0.f, 0.f, 0.f);

    for (int jt = 0; jt <= qi; jt++) {
        __syncthreads();
        const float* Kt = Kbase + (size_t)jt * 64 * HD;
        const float* Vt = Vbase + (size_t)jt * 64 * HD;
#pragma unroll
        for (int p = t; p < 64 * 32; p += 256) {
            int n = p >> 5, c4 = (p & 31) * 4;
            float4 kv = *(const float4*)(Kt + n * HD + c4);
            Ks[(c4 + 0) * QP + n] = kv.x;
            Ks[(c4 + 1) * QP + n] = kv.y;
            Ks[(c4 + 2) * QP + n] = kv.z;
            Ks[(c4 + 3) * QP + n] = kv.w;
            float4 vv = *(const float4*)(Vt + n * HD + c4);
            *(float4*)(Vs + n * VP + c4) = vv;
        }
        __syncthreads();

        float acc[4][4];
#pragma unroll
        for (int i = 0; i < 4; i++)
#pragma unroll
            for (int j = 0; j < 4; j++) acc[i][j] = 0.f;
        for (int d = 0; d < HD; d++) {
            float4 qa = *(const float4*)(Qs + d * QP + ty * 4);
            float4 kb = *(const float4*)(Ks + d * QP + tx * 4);
            float av[4] = {qa.x, qa.y, qa.z, qa.w};
            float bv[4] = {kb.x, kb.y, kb.z, kb.w};
#pragma unroll
            for (int i = 0; i < 4; i++)
#pragma unroll
                for (int j = 0; j < 4; j++)
                    acc[i][j] = fmaf(av[i], bv[j], acc[i][j]);
        }
        const int kbase = jt * 64;
#pragma unroll
        for (int i = 0; i < 4; i++) {
            int qrow = qi * 64 + ty * 4 + i;
            float4 sv;
            sv.x = acc[i][0] * scale + ((kbase + tx * 4 + 0) > qrow ? -1e9f : 0.f);
            sv.y = acc[i][1] * scale + ((kbase + tx * 4 + 1) > qrow ? -1e9f : 0.f);
            sv.z = acc[i][2] * scale + ((kbase + tx * 4 + 2) > qrow ? -1e9f : 0.f);
            sv.w = acc[i][3] * scale + ((kbase + tx * 4 + 3) > qrow ? -1e9f : 0.f);
            *(float4*)(Ss + (ty * 4 + i) * SP + tx * 4) = sv;
        }
        __syncthreads();

        float* srow = Ss + r * SP + qq * 16;
        float mloc = -INFINITY;
#pragma unroll
        for (int n = 0; n < 16; n++) mloc = fmaxf(mloc, srow[n]);
        mloc = fmaxf(mloc, __shfl_xor_sync(0xffffffffu, mloc, 1));
        mloc = fmaxf(mloc, __shfl_xor_sync(0xffffffffu, mloc, 2));
        float mnew = fmaxf(mrun, mloc);
        float corr = __expf(mrun - mnew);
        float lsum = 0.f;
#pragma unroll
        for (int n = 0; n < 16; n++) {
            float pe = __expf(srow[n] - mnew);
            srow[n] = pe;
            lsum += pe;
        }
        lsum += __shfl_xor_sync(0xffffffffu, lsum, 1);
        lsum += __shfl_xor_sync(0xffffffffu, lsum, 2);
        lrun = lrun * corr + lsum;
        mrun = mnew;
        __syncwarp();

#pragma unroll
        for (int j = 0; j < 8; j++) {
            o[j].x *= corr; o[j].y *= corr; o[j].z *= corr; o[j].w *= corr;
        }
        const float* prow = Ss + r * SP;
        for (int n = 0; n < 64; n++) {
            float pp = prow[n];
            const float4* vr = (const float4*)(Vs + n * VP) + qq;
#pragma unroll
            for (int j = 0; j < 8; j++) {
                float4 vv = vr[4 * j];
                o[j].x = fmaf(pp, vv.x, o[j].x);
                o[j].y = fmaf(pp, vv.y, o[j].y);
                o[j].z = fmaf(pp, vv.z, o[j].z);
                o[j].w = fmaf(pp, vv.w, o[j].w);
            }
        }
    }

    float invl = 1.f / lrun;
    int qrow = qi * 64 + r;
    float* op = Out + ((size_t)(b * SEQ + qrow)) * (NH * HD) + h * HD;
#pragma unroll
    for (int j = 0; j < 8; j++) {
        float4 v = o[j];
        v.x *= invl; v.y *= invl; v.z *= invl; v.w *= invl;
        *(float4*)(op + (qq + 4 * j) * 4) = v;
    }
}

// ---------------- launch -----------------------------------------------------
extern "C" void kernel_launch(void* const* d_in, const int* in_sizes, int n_in,
                              void* d_out, int out_size) {
    (void)in_sizes; (void)n_in; (void)out_size;
    const float* x  = (const float*)d_in[0];
    const float* Wq = (const float*)d_in[1];
    const float* Wk = (const float*)d_in[2];
    const float* Wv = (const float*)d_in[3];
    const float* Wo = (const float*)d_in[4];
    const float* qg = (const float*)d_in[5];
    const float* kg = (const float*)d_in[6];
    const float* cs = (const float*)d_in[7];
    const float* sn = (const float*)d_in[8];
    float* out = (float*)d_out;

    float *qb, *kb, *vb, *Qt, *Kt, *Vt, *attnb, *WqT, *WkT, *WvT, *WoT;
    cudaGetSymbolAddress((void**)&qb,    g_qbuf);
    cudaGetSymbolAddress((void**)&kb,    g_kbuf);
    cudaGetSymbolAddress((void**)&vb,    g_vbuf);
    cudaGetSymbolAddress((void**)&Qt,    g_Qt);
    cudaGetSymbolAddress((void**)&Kt,    g_Kt);
    cudaGetSymbolAddress((void**)&Vt,    g_Vt);
    cudaGetSymbolAddress((void**)&attnb, g_attn);
    cudaGetSymbolAddress((void**)&WqT,   g_WqT);
    cudaGetSymbolAddress((void**)&WkT,   g_WkT);
    cudaGetSymbolAddress((void**)&WvT,   g_WvT);
    cudaGetSymbolAddress((void**)&WoT,   g_WoT);

    const int M = BATCH * SEQ;  // 4096

    cudaFuncSetAttribute(flash_k, cudaFuncAttributeMaxDynamicSharedMemorySize, FA_SMEM);

    // weight transposes (cheap, bandwidth-bound)
    transpose_k<<<dim3(DIMC / 32, DIMC / 32), 256>>>(Wq, WqT, DIMC, DIMC);
    transpose_k<<<dim3((NKV * HD) / 32, DIMC / 32), 256>>>(Wk, WkT, DIMC, NKV * HD);
    transpose_k<<<dim3((NKV * HD) / 32, DIMC / 32), 256>>>(Wv, WvT, DIMC, NKV * HD);
    transpose_k<<<dim3(DIMC / 32, DIMC / 32), 256>>>(Wo, WoT, DIMC, DIMC);

    // projections on tensor cores (3xTF32 via mma.sync)
    tf32gemm<<<dim3((NH * HD) / 128,  M / 128), 256>>>(x, WqT, qb, NH * HD,  DIMC);
    tf32gemm<<<dim3((NKV * HD) / 128, M / 128), 256>>>(x, WkT, kb, NKV * HD, DIMC);
    tf32gemm<<<dim3((NKV * HD) / 128, M / 128), 256>>>(x, WvT, vb, NKV * HD, DIMC);

    rmsnorm_rope_k<<<(M * NH)  / 8, 256>>>(qb, qg, cs, sn, Qt, NH,  M * NH);
    rmsnorm_rope_k<<<(M * NKV) / 8, 256>>>(kb, kg, cs, sn, Kt, NKV, M * NKV);
    vtrans_k<<<(M * NKV * HD / 4) / 256, 256>>>(vb, Vt);

    flash_k<<<dim3(SEQ / 64, NH, BATCH), 256, FA_SMEM>>>(Qt, Kt, Vt, attnb);

    tf32gemm<<<dim3(DIMC / 128, M / 128), 256>>>(attnb, WoT, out, DIMC, DIMC);
}

// round 4
// speedup vs baseline: 2.7177x; 2.2475x over previous
#include <cuda_runtime.h>
#include <cuda_bf16.h>
#include <math.h>
#include <stdint.h>

#define DIMC   2048
#define NH     16
#define NKV    4
#define SEQ    2048
#define BATCH  2
#define HD     128

// ---------------- scratch (static device memory; no allocs) ----------------
__device__ float g_qbuf[BATCH*SEQ*NH*HD];
__device__ float g_kbuf[BATCH*SEQ*NKV*HD];
__device__ float g_vbuf[BATCH*SEQ*NKV*HD];
__device__ float g_attn[BATCH*SEQ*NH*HD];
__device__ float g_WqT[DIMC*DIMC];
__device__ float g_WkT[NKV*HD*DIMC];
__device__ float g_WvT[NKV*HD*DIMC];
__device__ float g_WoT[DIMC*DIMC];
__device__ __nv_bfloat16 g_Qh[BATCH*NH*SEQ*HD];
__device__ __nv_bfloat16 g_Ql[BATCH*NH*SEQ*HD];
__device__ __nv_bfloat16 g_Kh[BATCH*NKV*SEQ*HD];
__device__ __nv_bfloat16 g_Kl[BATCH*NKV*SEQ*HD];
__device__ __nv_bfloat16 g_Vh[BATCH*NKV*HD*SEQ];
__device__ __nv_bfloat16 g_Vl[BATCH*NKV*HD*SEQ];

// ================= helpers =================
__device__ __forceinline__ void mma16(float* c, const uint32_t* a, const uint32_t* b) {
    asm volatile(
        "mma.sync.aligned.m16n8k16.row.col.f32.bf16.bf16.f32 "
        "{%0,%1,%2,%3}, {%4,%5,%6,%7}, {%8,%9}, {%0,%1,%2,%3};"
        : "+f"(c[0]), "+f"(c[1]), "+f"(c[2]), "+f"(c[3])
        : "r"(a[0]), "r"(a[1]), "r"(a[2]), "r"(a[3]), "r"(b[0]), "r"(b[1]));
}
// pack (x -> low half, y -> high half) as bf16x2, plus residual pair
__device__ __forceinline__ void split2(float x, float y, uint32_t& h, uint32_t& l) {
    __nv_bfloat16 hx = __float2bfloat16(x), hy = __float2bfloat16(y);
    float rx = x - __bfloat162float(hx);
    float ry = y - __bfloat162float(hy);
    __nv_bfloat16 lx = __float2bfloat16(rx), ly = __float2bfloat16(ry);
    h = ((uint32_t)__bfloat16_as_ushort(hy) << 16) | (uint32_t)__bfloat16_as_ushort(hx);
    l = ((uint32_t)__bfloat16_as_ushort(ly) << 16) | (uint32_t)__bfloat16_as_ushort(lx);
}

// ================= bf16x3 GEMM via mma.sync =================
// C[M,N] = A[M,K] @ Bt[N,K]^T. 128x128 tile, BK=32, 256 thr, warp tile 32x64.
// smem stride 72 bf16 = 144B  (144/4 = 36 ≡ 4 mod 32 -> conflict-free frags)
#define GSTR 72
#define GEMM_SMEM (4 * 128 * GSTR * 2)

__global__ void __launch_bounds__(256) bf16gemm(const float* __restrict__ A,
                                                const float* __restrict__ Bt,
                                                float* __restrict__ C,
                                                int N, int K) {
    extern __shared__ __nv_bfloat16 gsm[];
    __nv_bfloat16* Ah = gsm;
    __nv_bfloat16* Al = gsm + 128 * GSTR;
    __nv_bfloat16* Bh = gsm + 2 * 128 * GSTR;
    __nv_bfloat16* Bl = gsm + 3 * 128 * GSTR;

    const int t = threadIdx.x;
    const int wid = t >> 5, lane = t & 31;
    const int g = lane >> 2, tig = lane & 3;
    const int wm = wid & 3, wn = wid >> 2;
    const int m0w = wm * 32, n0w = wn * 64;
    const int row0 = blockIdx.y * 128, col0 = blockIdx.x * 128;
    const int tk = t & 7, tm = t >> 3;
    const float* Ag = A  + (size_t)(row0 + tm) * K + tk * 4;
    const float* Bg = Bt + (size_t)(col0 + tm) * K + tk * 4;

    float acc[2][8][4];
#pragma unroll
    for (int mf = 0; mf < 2; mf++)
#pragma unroll
        for (int nf = 0; nf < 8; nf++)
#pragma unroll
            for (int e = 0; e < 4; e++) acc[mf][nf][e] = 0.f;

    float4 pa[4], pb[4];
#pragma unroll
    for (int i = 0; i < 4; i++) {
        pa[i] = *(const float4*)(Ag + (size_t)(32 * i) * K);
        pb[i] = *(const float4*)(Bg + (size_t)(32 * i) * K);
    }

    const int CH = K / 32;
    for (int c = 0; c < CH; c++) {
        __syncthreads();
#pragma unroll
        for (int i = 0; i < 4; i++) {
            int row = tm + 32 * i;
            uint2 h2, l2;
            split2(pa[i].x, pa[i].y, h2.x, l2.x);
            split2(pa[i].z, pa[i].w, h2.y, l2.y);
            *(uint2*)&Ah[row * GSTR + tk * 4] = h2;
            *(uint2*)&Al[row * GSTR + tk * 4] = l2;
            split2(pb[i].x, pb[i].y, h2.x, l2.x);
            split2(pb[i].z, pb[i].w, h2.y, l2.y);
            *(uint2*)&Bh[row * GSTR + tk * 4] = h2;
            *(uint2*)&Bl[row * GSTR + tk * 4] = l2;
        }
        __syncthreads();
        if (c + 1 < CH) {
            const int k0 = (c + 1) * 32;
#pragma unroll
            for (int i = 0; i < 4; i++) {
                pa[i] = *(const float4*)(Ag + k0 + (size_t)(32 * i) * K);
                pb[i] = *(const float4*)(Bg + k0 + (size_t)(32 * i) * K);
            }
        }
#pragma unroll
        for (int kk = 0; kk < 2; kk++) {
            const int kc = kk * 16 + 2 * tig;
            uint32_t ah[2][4], al[2][4];
#pragma unroll
            for (int mf = 0; mf < 2; mf++) {
                int r = (m0w + mf * 16 + g) * GSTR;
                ah[mf][0] = *(const uint32_t*)&Ah[r + kc];
                ah[mf][1] = *(const uint32_t*)&Ah[r + 8 * GSTR + kc];
                ah[mf][2] = *(const uint32_t*)&Ah[r + kc + 8];
                ah[mf][3] = *(const uint32_t*)&Ah[r + 8 * GSTR + kc + 8];
                al[mf][0] = *(const uint32_t*)&Al[r + kc];
                al[mf][1] = *(const uint32_t*)&Al[r + 8 * GSTR + kc];
                al[mf][2] = *(const uint32_t*)&Al[r + kc + 8];
                al[mf][3] = *(const uint32_t*)&Al[r + 8 * GSTR + kc + 8];
            }
#pragma unroll
            for (int nf = 0; nf < 8; nf++) {
                int r = (n0w + nf * 8 + g) * GSTR;
                uint32_t bh[2], bl[2];
                bh[0] = *(const uint32_t*)&Bh[r + kc];
                bh[1] = *(const uint32_t*)&Bh[r + kc + 8];
                bl[0] = *(const uint32_t*)&Bl[r + kc];
                bl[1] = *(const uint32_t*)&Bl[r + kc + 8];
#pragma unroll
                for (int mf = 0; mf < 2; mf++) {
                    mma16(acc[mf][nf], ah[mf], bh);
                    mma16(acc[mf][nf], al[mf], bh);
                    mma16(acc[mf][nf], ah[mf], bl);
                }
            }
        }
    }

#pragma unroll
    for (int mf = 0; mf < 2; mf++)
#pragma unroll
        for (int nf = 0; nf < 8; nf++) {
            int r0 = row0 + m0w + mf * 16 + g;
            int cc = col0 + n0w + nf * 8 + 2 * tig;
            *(float2*)(C + (size_t)r0 * N + cc) = make_float2(acc[mf][nf][0], acc[mf][nf][1]);
            *(float2*)(C + (size_t)(r0 + 8) * N + cc) = make_float2(acc[mf][nf][2], acc[mf][nf][3]);
        }
}

// ---------------- W transpose: Wt[n][k] = W[k][n] ---------------------------
__global__ void __launch_bounds__(256) transpose_k(const float* __restrict__ W,
                                                   float* __restrict__ Wt,
                                                   int K, int N) {
    __shared__ float tile[32][33];
    int n0 = blockIdx.x * 32, k0 = blockIdx.y * 32;
    int tx = threadIdx.x & 31, ty = threadIdx.x >> 5;
#pragma unroll
    for (int i = ty; i < 32; i += 8)
        tile[i][tx] = W[(size_t)(k0 + i) * N + n0 + tx];
    __syncthreads();
#pragma unroll
    for (int i = ty; i < 32; i += 8)
        Wt[(size_t)(n0 + i) * K + k0 + tx] = tile[tx][i];
}

// ---------------- RMSNorm + RoPE + head transpose + bf16 split -------------
// in: [B*S, nh, HD] -> out hi/lo bf16 [B, nh, S, HD]
__global__ void __launch_bounds__(256) rmsnorm_rope_k(const float* __restrict__ in,
        const float* __restrict__ g, const float* __restrict__ cs,
        const float* __restrict__ sn, __nv_bfloat16* __restrict__ outh,
        __nv_bfloat16* __restrict__ outl, int nh, int nrows) {
    int w = (blockIdx.x * 256 + threadIdx.x) >> 5;
    if (w >= nrows) return;
    int lane = threadIdx.x & 31;
    int h  = w % nh;
    int bs = w / nh;
    int b = bs / SEQ, s = bs % SEQ;
    int d = lane * 4;
    const float* row = in + (size_t)w * HD;
    float4 v = *(const float4*)(row + d);
    float ssq = v.x * v.x + v.y * v.y + v.z * v.z + v.w * v.w;
#pragma unroll
    for (int o = 16; o; o >>= 1) ssq += __shfl_xor_sync(0xffffffffu, ssq, o);
    float inv = rsqrtf(ssq * (1.f / HD) + 1e-6f);
    float4 gv = *(const float4*)(g + d);
    float y[4];
    y[0] = v.x * inv * gv.x;  y[1] = v.y * inv * gv.y;
    y[2] = v.z * inv * gv.z;  y[3] = v.w * inv * gv.w;
    float p[4];
#pragma unroll
    for (int i = 0; i < 4; i++) p[i] = __shfl_xor_sync(0xffffffffu, y[i], 16);
    float sgn = (lane < 16) ? -1.f : 1.f;
    float4 cv = *(const float4*)(cs + (size_t)s * HD + d);
    float4 sv = *(const float4*)(sn + (size_t)s * HD + d);
    float o0 = y[0] * cv.x + sgn * p[0] * sv.x;
    float o1 = y[1] * cv.y + sgn * p[1] * sv.y;
    float o2 = y[2] * cv.z + sgn * p[2] * sv.z;
    float o3 = y[3] * cv.w + sgn * p[3] * sv.w;
    uint2 h2, l2;
    split2(o0, o1, h2.x, l2.x);
    split2(o2, o3, h2.y, l2.y);
    size_t oidx = ((size_t)(b * nh + h) * SEQ + s) * HD + d;
    *(uint2*)(outh + oidx) = h2;
    *(uint2*)(outl + oidx) = l2;
}

// ---------------- V transpose + bf16 split ----------------------------------
// in: [B*S, KV*HD] f32 -> out hi/lo bf16 [B, KV, HD, SEQ]
__global__ void __launch_bounds__(256) vtrans_k(const float* __restrict__ in,
        __nv_bfloat16* __restrict__ outh, __nv_bfloat16* __restrict__ outl) {
    __shared__ float tile[32][33];
    int s0 = blockIdx.x * 32, d0 = blockIdx.y * 32;
    int bkv = blockIdx.z;                    // b*NKV + kv
    int b = bkv >> 2, kv = bkv & 3;
    int tx = threadIdx.x & 31, ty = threadIdx.x >> 5;
#pragma unroll
    for (int i = ty; i < 32; i += 8)
        tile[i][tx] = in[(size_t)(b * SEQ + s0 + i) * (NKV * HD) + kv * HD + d0 + tx];
    __syncthreads();
#pragma unroll
    for (int i = ty; i < 32; i += 8) {
        float v = tile[tx][i];               // element (s = s0+tx, d = d0+i)
        __nv_bfloat16 hv = __float2bfloat16(v);
        __nv_bfloat16 lv = __float2bfloat16(v - __bfloat162float(hv));
        size_t oidx = ((size_t)bkv * HD + d0 + i) * SEQ + s0 + tx;
        outh[oidx] = hv;
        outl[oidx] = lv;
    }
}

// ---------------- Flash attention on mma.sync (bf16x3, causal) --------------
// Q,K hi/lo: [B,{NH|KV},S,HD] bf16 ; V hi/lo: [B,KV,HD,S] bf16 ; Out f32 [B*S, NH*HD]
// CTA: 128 threads (4 warps), BM=64, BN=64. Warp w owns Q rows w*16..w*16+15.
#define QSTR 136   // 272B rows: conflict-free fragment loads
#define VSTR 72    // 144B rows
#define FA_Q  (64 * QSTR)
#define FA_K  (64 * QSTR)
#define FA_V  (128 * VSTR)
#define FA_SMEM ((2 * FA_Q + 2 * FA_K + 2 * FA_V) * 2)

__global__ void __launch_bounds__(128) flash_mma(
        const __nv_bfloat16* __restrict__ Qh, const __nv_bfloat16* __restrict__ Ql,
        const __nv_bfloat16* __restrict__ Kh, const __nv_bfloat16* __restrict__ Kl,
        const __nv_bfloat16* __restrict__ Vh, const __nv_bfloat16* __restrict__ Vl,
        float* __restrict__ Out) {
    extern __shared__ __align__(16) __nv_bfloat16 fsm[];
    __nv_bfloat16* sQh = fsm;
    __nv_bfloat16* sQl = fsm + FA_Q;
    __nv_bfloat16* sKh = fsm + 2 * FA_Q;
    __nv_bfloat16* sKl = fsm + 2 * FA_Q + FA_K;
    __nv_bfloat16* sVh = fsm + 2 * FA_Q + 2 * FA_K;
    __nv_bfloat16* sVl = fsm + 2 * FA_Q + 2 * FA_K + FA_V;

    const int t = threadIdx.x, w = t >> 5, lane = t & 31;
    const int g = lane >> 2, tig = lane & 3;
    const int qi = gridDim.x - 1 - blockIdx.x;   // big tiles first
    const int h = blockIdx.y, b = blockIdx.z;
    const int kvh = h >> 2;
    const int m0 = w * 16;
    const float scale = 0.08838834764831845f;

    const __nv_bfloat16* Qgh = Qh + ((size_t)(b * NH + h) * SEQ + qi * 64) * HD;
    const __nv_bfloat16* Qgl = Ql + ((size_t)(b * NH + h) * SEQ + qi * 64) * HD;
    const __nv_bfloat16* Kbh = Kh + (size_t)(b * NKV + kvh) * SEQ * HD;
    const __nv_bfloat16* Kbl = Kl + (size_t)(b * NKV + kvh) * SEQ * HD;
    const __nv_bfloat16* Vbh = Vh + (size_t)(b * NKV + kvh) * HD * SEQ;
    const __nv_bfloat16* Vbl = Vl + (size_t)(b * NKV + kvh) * HD * SEQ;

    // load Q tile (64 x 128) hi/lo
#pragma unroll
    for (int p = t; p < 64 * 16; p += 128) {
        int m = p >> 4, c8 = (p & 15) * 8;
        *(uint4*)&sQh[m * QSTR + c8] = *(const uint4*)(Qgh + (size_t)m * HD + c8);
        *(uint4*)&sQl[m * QSTR + c8] = *(const uint4*)(Qgl + (size_t)m * HD + c8);
    }

    float o[16][4];
#pragma unroll
    for (int nf = 0; nf < 16; nf++)
#pragma unroll
        for (int e = 0; e < 4; e++) o[nf][e] = 0.f;
    float mrun0 = -INFINITY, mrun1 = -INFINITY, lrun0 = 0.f, lrun1 = 0.f;

    for (int jt = 0; jt <= qi; jt++) {
        __syncthreads();
        // load K tile (64 x 128) and V tile (128 x 64, d-major)
        const __nv_bfloat16* Kth = Kbh + (size_t)jt * 64 * HD;
        const __nv_bfloat16* Ktl = Kbl + (size_t)jt * 64 * HD;
#pragma unroll
        for (int p = t; p < 64 * 16; p += 128) {
            int n = p >> 4, c8 = (p & 15) * 8;
            *(uint4*)&sKh[n * QSTR + c8] = *(const uint4*)(Kth + (size_t)n * HD + c8);
            *(uint4*)&sKl[n * QSTR + c8] = *(const uint4*)(Ktl + (size_t)n * HD + c8);
        }
        const __nv_bfloat16* Vth = Vbh + jt * 64;
        const __nv_bfloat16* Vtl = Vbl + jt * 64;
#pragma unroll
        for (int p = t; p < 128 * 8; p += 128) {
            int d = p >> 3, c8 = (p & 7) * 8;
            *(uint4*)&sVh[d * VSTR + c8] = *(const uint4*)(Vth + (size_t)d * SEQ + c8);
            *(uint4*)&sVl[d * VSTR + c8] = *(const uint4*)(Vtl + (size_t)d * SEQ + c8);
        }
        __syncthreads();

        // ---- S = Q K^T (warp: 16x64) ----
        float s[8][4];
#pragma unroll
        for (int nf = 0; nf < 8; nf++)
#pragma unroll
            for (int e = 0; e < 4; e++) s[nf][e] = 0.f;
#pragma unroll
        for (int kk = 0; kk < 8; kk++) {
            const int kc = kk * 16 + 2 * tig;
            uint32_t ah[4], al[4];
            {
                int r = (m0 + g) * QSTR;
                ah[0] = *(const uint32_t*)&sQh[r + kc];
                ah[1] = *(const uint32_t*)&sQh[r + 8 * QSTR + kc];
                ah[2] = *(const uint32_t*)&sQh[r + kc + 8];
                ah[3] = *(const uint32_t*)&sQh[r + 8 * QSTR + kc + 8];
                al[0] = *(const uint32_t*)&sQl[r + kc];
                al[1] = *(const uint32_t*)&sQl[r + 8 * QSTR + kc];
                al[2] = *(const uint32_t*)&sQl[r + kc + 8];
                al[3] = *(const uint32_t*)&sQl[r + 8 * QSTR + kc + 8];
            }
#pragma unroll
            for (int nf = 0; nf < 8; nf++) {
                int r = (nf * 8 + g) * QSTR;
                uint32_t bh[2], bl[2];
                bh[0] = *(const uint32_t*)&sKh[r + kc];
                bh[1] = *(const uint32_t*)&sKh[r + kc + 8];
                bl[0] = *(const uint32_t*)&sKl[r + kc];
                bl[1] = *(const uint32_t*)&sKl[r + kc + 8];
                mma16(s[nf], ah, bh);
                mma16(s[nf], al, bh);
                mma16(s[nf], ah, bl);
            }
        }

        // ---- scale + causal mask + online softmax (in registers) ----
        const int rowg = qi * 64 + m0 + g;
        const bool diag = (jt == qi);
#pragma unroll
        for (int nf = 0; nf < 8; nf++) {
            int colb = jt * 64 + nf * 8 + 2 * tig;
#pragma unroll
            for (int e = 0; e < 4; e++) {
                float v = s[nf][e] * scale;
                if (diag && (colb + (e & 1)) > (rowg + (e >> 1) * 8)) v -= 1e9f;
                s[nf][e] = v;
            }
        }
        float ml0 = -INFINITY, ml1 = -INFINITY;
#pragma unroll
        for (int nf = 0; nf < 8; nf++) {
            ml0 = fmaxf(ml0, fmaxf(s[nf][0], s[nf][1]));
            ml1 = fmaxf(ml1, fmaxf(s[nf][2], s[nf][3]));
        }
        ml0 = fmaxf(ml0, __shfl_xor_sync(0xffffffffu, ml0, 1));
        ml0 = fmaxf(ml0, __shfl_xor_sync(0xffffffffu, ml0, 2));
        ml1 = fmaxf(ml1, __shfl_xor_sync(0xffffffffu, ml1, 1));
        ml1 = fmaxf(ml1, __shfl_xor_sync(0xffffffffu, ml1, 2));
        float mn0 = fmaxf(mrun0, ml0), mn1 = fmaxf(mrun1, ml1);
        float c0 = __expf(mrun0 - mn0), c1 = __expf(mrun1 - mn1);
        float ls0 = 0.f, ls1 = 0.f;
#pragma unroll
        for (int nf = 0; nf < 8; nf++) {
            s[nf][0] = __expf(s[nf][0] - mn0);
            s[nf][1] = __expf(s[nf][1] - mn0);
            s[nf][2] = __expf(s[nf][2] - mn1);
            s[nf][3] = __expf(s[nf][3] - mn1);
            ls0 += s[nf][0] + s[nf][1];
            ls1 += s[nf][2] + s[nf][3];
        }
        ls0 += __shfl_xor_sync(0xffffffffu, ls0, 1);
        ls0 += __shfl_xor_sync(0xffffffffu, ls0, 2);
        ls1 += __shfl_xor_sync(0xffffffffu, ls1, 1);
        ls1 += __shfl_xor_sync(0xffffffffu, ls1, 2);
        lrun0 = lrun0 * c0 + ls0;
        lrun1 = lrun1 * c1 + ls1;
        mrun0 = mn0; mrun1 = mn1;
#pragma unroll
        for (int nf = 0; nf < 16; nf++) {
            o[nf][0] *= c0; o[nf][1] *= c0;
            o[nf][2] *= c1; o[nf][3] *= c1;
        }

        // ---- pack P (S accum frags) into A frags for PV ----
        uint32_t pah[4][4], pal[4][4];
#pragma unroll
        for (int kk2 = 0; kk2 < 4; kk2++) {
            split2(s[2*kk2][0],   s[2*kk2][1],   pah[kk2][0], pal[kk2][0]);
            split2(s[2*kk2][2],   s[2*kk2][3],   pah[kk2][1], pal[kk2][1]);
            split2(s[2*kk2+1][0], s[2*kk2+1][1], pah[kk2][2], pal[kk2][2]);
            split2(s[2*kk2+1][2], s[2*kk2+1][3], pah[kk2][3], pal[kk2][3]);
        }

        // ---- O += P @ V (warp: 16x128) ----
#pragma unroll
        for (int nf2 = 0; nf2 < 16; nf2++) {
            int r = (nf2 * 8 + g) * VSTR;
#pragma unroll
            for (int kk2 = 0; kk2 < 4; kk2++) {
                uint32_t bh[2], bl[2];
                bh[0] = *(const uint32_t*)&sVh[r + kk2 * 16 + 2 * tig];
                bh[1] = *(const uint32_t*)&sVh[r + kk2 * 16 + 8 + 2 * tig];
                bl[0] = *(const uint32_t*)&sVl[r + kk2 * 16 + 2 * tig];
                bl[1] = *(const uint32_t*)&sVl[r + kk2 * 16 + 8 + 2 * tig];
                mma16(o[nf2], pah[kk2], bh);
                mma16(o[nf2], pal[kk2], bh);
                mma16(o[nf2], pah[kk2], bl);
            }
        }
    }

    float il0 = 1.f / lrun0, il1 = 1.f / lrun1;
    int qrow = qi * 64 + m0 + g;
    float* op0 = Out + (size_t)(b * SEQ + qrow) * (NH * HD) + h * HD;
    float* op1 = op0 + (size_t)8 * (NH * HD);
#pragma unroll
    for (int nf2 = 0; nf2 < 16; nf2++) {
        *(float2*)(op0 + nf2 * 8 + 2 * tig) = make_float2(o[nf2][0] * il0, o[nf2][1] * il0);
        *(float2*)(op1 + nf2 * 8 + 2 * tig) = make_float2(o[nf2][2] * il1, o[nf2][3] * il1);
    }
}

// ---------------- launch -----------------------------------------------------
extern "C" void kernel_launch(void* const* d_in, const int* in_sizes, int n_in,
                              void* d_out, int out_size) {
    (void)in_sizes; (void)n_in; (void)out_size;
    const float* x  = (const float*)d_in[0];
    const float* Wq = (const float*)d_in[1];
    const float* Wk = (const float*)d_in[2];
    const float* Wv = (const float*)d_in[3];
    const float* Wo = (const float*)d_in[4];
    const float* qg = (const float*)d_in[5];
    const float* kg = (const float*)d_in[6];
    const float* cs = (const float*)d_in[7];
    const float* sn = (const float*)d_in[8];
    float* out = (float*)d_out;

    float *qb, *kb, *vb, *attnb, *WqT, *WkT, *WvT, *WoT;
    __nv_bfloat16 *Qh, *Ql, *Kh, *Kl, *Vh, *Vl;
    cudaGetSymbolAddress((void**)&qb,    g_qbuf);
    cudaGetSymbolAddress((void**)&kb,    g_kbuf);
    cudaGetSymbolAddress((void**)&vb,    g_vbuf);
    cudaGetSymbolAddress((void**)&attnb, g_attn);
    cudaGetSymbolAddress((void**)&WqT,   g_WqT);
    cudaGetSymbolAddress((void**)&WkT,   g_WkT);
    cudaGetSymbolAddress((void**)&WvT,   g_WvT);
    cudaGetSymbolAddress((void**)&WoT,   g_WoT);
    cudaGetSymbolAddress((void**)&Qh,    g_Qh);
    cudaGetSymbolAddress((void**)&Ql,    g_Ql);
    cudaGetSymbolAddress((void**)&Kh,    g_Kh);
    cudaGetSymbolAddress((void**)&Kl,    g_Kl);
    cudaGetSymbolAddress((void**)&Vh,    g_Vh);
    cudaGetSymbolAddress((void**)&Vl,    g_Vl);

    const int M = BATCH * SEQ;  // 4096

    cudaFuncSetAttribute(bf16gemm,  cudaFuncAttributeMaxDynamicSharedMemorySize, GEMM_SMEM);
    cudaFuncSetAttribute(flash_mma, cudaFuncAttributeMaxDynamicSharedMemorySize, FA_SMEM);

    transpose_k<<<dim3(DIMC / 32, DIMC / 32), 256>>>(Wq, WqT, DIMC, DIMC);
    transpose_k<<<dim3((NKV * HD) / 32, DIMC / 32), 256>>>(Wk, WkT, DIMC, NKV * HD);
    transpose_k<<<dim3((NKV * HD) / 32, DIMC / 32), 256>>>(Wv, WvT, DIMC, NKV * HD);
    transpose_k<<<dim3(DIMC / 32, DIMC / 32), 256>>>(Wo, WoT, DIMC, DIMC);

    bf16gemm<<<dim3((NH * HD) / 128,  M / 128), 256, GEMM_SMEM>>>(x, WqT, qb, NH * HD,  DIMC);
    bf16gemm<<<dim3((NKV * HD) / 128, M / 128), 256, GEMM_SMEM>>>(x, WkT, kb, NKV * HD, DIMC);
    bf16gemm<<<dim3((NKV * HD) / 128, M / 128), 256, GEMM_SMEM>>>(x, WvT, vb, NKV * HD, DIMC);

    rmsnorm_rope_k<<<(M * NH)  / 8, 256>>>(qb, qg, cs, sn, Qh, Ql, NH,  M * NH);
    rmsnorm_rope_k<<<(M * NKV) / 8, 256>>>(kb, kg, cs, sn, Kh, Kl, NKV, M * NKV);
    vtrans_k<<<dim3(SEQ / 32, HD / 32, BATCH * NKV), 256>>>(vb, Vh, Vl);

    flash_mma<<<dim3(SEQ / 64, NH, BATCH), 128, FA_SMEM>>>(Qh, Ql, Kh, Kl, Vh, Vl, attnb);

    bf16gemm<<<dim3(DIMC / 128, M / 128), 256, GEMM_SMEM>>>(attnb, WoT, out, DIMC, DIMC);
}